// round 4
// baseline (speedup 1.0000x reference)
#include <cuda_runtime.h>
#include <cuda_bf16.h>

#define NAG 4096
#define H   64
#define CAP 128   // per-row neighbor capacity (Poisson(32) max over 4096 rows << 128)

// ---------------- device scratch (no allocations allowed) ----------------
__device__ int   g_cnt[NAG];
__device__ int   g_list[NAG * CAP];
__device__ float g_x[NAG * H];     // embedding output (kept for residual)
__device__ float g_h[NAG * H];     // layer io
__device__ float g_hw[NAG * H];    // h @ W
__device__ float g_ssrc[NAG];
__device__ float g_sdst[NAG];
__device__ float g_s[NAG];         // per-row layernorm'd dot with val_w

// ---------------- kernels ----------------

__global__ void k_reset() {
    int i = blockIdx.x * blockDim.x + threadIdx.x;
    if (i < NAG) g_cnt[i] = 0;
}

// mask[i][j] = adj[j][i] != 0 (plus self-loop handled in aggregation).
// One float4 per thread over the 64MB adjacency, coalesced.
__global__ void k_build(const float4* __restrict__ adj) {
    int idx = blockIdx.x * blockDim.x + threadIdx.x;   // 0 .. N*N/4-1
    int j  = idx >> 10;            // adjacency row (source node)
    int i0 = (idx & 1023) << 2;    // column base (destination node)
    float4 v = adj[idx];
    float vv[4] = {v.x, v.y, v.z, v.w};
#pragma unroll
    for (int t = 0; t < 4; t++) {
        int i = i0 + t;
        if (vv[t] != 0.0f && i != j) {
            int slot = atomicAdd(&g_cnt[i], 1);
            if (slot < CAP) g_list[i * CAP + slot] = j;
        }
    }
}

__device__ __forceinline__ float decode_ts(const void* p) {
    int iv = *(const int*)p;
    if (iv > -1000000 && iv < 1000000) return (float)iv;  // int32 timestep
    return __int_as_float(iv);                            // float32 timestep
}

// x = (feat @ w1 + b1) @ w2 + b2 ; feat = [progress, hard]. 16 rows / block.
__global__ void k_emb(const void* __restrict__ tsp,
                      const float* __restrict__ arr, const float* __restrict__ dep,
                      const float* __restrict__ hard,
                      const float* __restrict__ w1, const float* __restrict__ b1,
                      const float* __restrict__ w2, const float* __restrict__ b2) {
    __shared__ float shW[64 * 64];
    __shared__ float shT[16 * 64];
    int tid = threadIdx.x;
    int r0 = blockIdx.x * 16;
#pragma unroll
    for (int p = 0; p < 16; p++) shW[tid + p * 256] = w2[tid + p * 256];
    float ts = decode_ts(tsp);
    int o = tid & 63, rq = tid >> 6;
#pragma unroll
    for (int rr = 0; rr < 4; rr++) {
        int rl = rq * 4 + rr;
        int row = r0 + rl;
        float a = arr[row];
        float pg = (ts - a) / (dep[row] - a);
        float q = hard[row];
        shT[rl * 64 + o] = pg * w1[o] + q * w1[64 + o] + b1[o];
    }
    __syncthreads();
    float a0 = 0.f, a1 = 0.f, a2 = 0.f, a3 = 0.f;
    int rb = rq * 4;
#pragma unroll
    for (int k = 0; k < 64; k++) {
        float wv = shW[k * 64 + o];
        a0 += shT[(rb + 0) * 64 + k] * wv;
        a1 += shT[(rb + 1) * 64 + k] * wv;
        a2 += shT[(rb + 2) * 64 + k] * wv;
        a3 += shT[(rb + 3) * 64 + k] * wv;
    }
    float bb = b2[o];
    g_x[(r0 + rb + 0) * 64 + o] = a0 + bb;
    g_x[(r0 + rb + 1) * 64 + o] = a1 + bb;
    g_x[(r0 + rb + 2) * 64 + o] = a2 + bb;
    g_x[(r0 + rb + 3) * 64 + o] = a3 + bb;
}

// g_hw = in @ W   (in = g_x for layer 0 else g_h). 16 rows / block.
__global__ void k_gemm(const float* __restrict__ W, int in_is_x) {
    __shared__ float shW[64 * 64];
    __shared__ float shIn[16 * 64];
    const float* __restrict__ in = in_is_x ? g_x : g_h;
    int tid = threadIdx.x;
    int r0 = blockIdx.x * 16;
#pragma unroll
    for (int p = 0; p < 16; p++) shW[tid + p * 256] = W[tid + p * 256];
#pragma unroll
    for (int p = 0; p < 4; p++) shIn[tid + p * 256] = in[r0 * 64 + tid + p * 256];
    __syncthreads();
    int o = tid & 63, rq = tid >> 6;
    float a0 = 0.f, a1 = 0.f, a2 = 0.f, a3 = 0.f;
    int rb = rq * 4;
#pragma unroll
    for (int k = 0; k < 64; k++) {
        float wv = shW[k * 64 + o];
        a0 += shIn[(rb + 0) * 64 + k] * wv;
        a1 += shIn[(rb + 1) * 64 + k] * wv;
        a2 += shIn[(rb + 2) * 64 + k] * wv;
        a3 += shIn[(rb + 3) * 64 + k] * wv;
    }
    g_hw[(r0 + rb + 0) * 64 + o] = a0;
    g_hw[(r0 + rb + 1) * 64 + o] = a1;
    g_hw[(r0 + rb + 2) * 64 + o] = a2;
    g_hw[(r0 + rb + 3) * 64 + o] = a3;
}

// ssrc[i] = hw[i] . asrc ; sdst[i] = hw[i] . adst. One warp per row.
__global__ void k_scores(const float* __restrict__ asrc, const float* __restrict__ adst) {
    int lane = threadIdx.x & 31;
    int row = (blockIdx.x * blockDim.x + threadIdx.x) >> 5;
    float a = g_hw[row * 64 + lane];
    float b = g_hw[row * 64 + 32 + lane];
    float s1 = a * asrc[lane] + b * asrc[32 + lane];
    float s2 = a * adst[lane] + b * adst[32 + lane];
#pragma unroll
    for (int off = 16; off; off >>= 1) {
        s1 += __shfl_xor_sync(0xFFFFFFFFu, s1, off);
        s2 += __shfl_xor_sync(0xFFFFFFFFu, s2, off);
    }
    if (lane == 0) { g_ssrc[row] = s1; g_sdst[row] = s2; }
}

// h[i] = softmax_j(leaky(ssrc[j]+sdst[i])) @ hw + b ; optional relu. Warp per row.
__global__ void k_agg(const float* __restrict__ bias, int dorelu) {
    __shared__ float shw[8][CAP];
    __shared__ int   shj[8][CAP];
    int lane = threadIdx.x & 31;
    int w = threadIdx.x >> 5;
    int row = blockIdx.x * 8 + w;
    int deg = min(g_cnt[row], CAP);
    float sd = g_sdst[row];
    for (int n = lane; n < deg; n += 32) {
        int j = g_list[row * CAP + n];
        float e = g_ssrc[j] + sd;
        e = (e >= 0.f) ? e : 0.2f * e;
        shw[w][n] = e;
        shj[w][n] = j;
    }
    float es = g_ssrc[row] + sd;          // self-loop
    es = (es >= 0.f) ? es : 0.2f * es;
    __syncwarp();
    float m = es;
    for (int n = lane; n < deg; n += 32) m = fmaxf(m, shw[w][n]);
#pragma unroll
    for (int off = 16; off; off >>= 1) m = fmaxf(m, __shfl_xor_sync(0xFFFFFFFFu, m, off));
    float part = 0.f;
    for (int n = lane; n < deg; n += 32) {
        float ww = expf(shw[w][n] - m);
        shw[w][n] = ww;
        part += ww;
    }
#pragma unroll
    for (int off = 16; off; off >>= 1) part += __shfl_xor_sync(0xFFFFFFFFu, part, off);
    float wself = expf(es - m);
    float denom = part + wself;
    __syncwarp();
    float acc0 = wself * g_hw[row * 64 + lane];
    float acc1 = wself * g_hw[row * 64 + 32 + lane];
    for (int n = 0; n < deg; n++) {
        float ww = shw[w][n];
        int j = shj[w][n];
        acc0 += ww * __ldg(&g_hw[j * 64 + lane]);
        acc1 += ww * __ldg(&g_hw[j * 64 + 32 + lane]);
    }
    float inv = 1.f / denom;
    float o0 = acc0 * inv + bias[lane];
    float o1 = acc1 * inv + bias[32 + lane];
    if (dorelu) { o0 = fmaxf(o0, 0.f); o1 = fmaxf(o1, 0.f); }
    g_h[row * 64 + lane] = o0;
    g_h[row * 64 + 32 + lane] = o1;
}

// z = x + h ; layernorm(z) ; s[i] = znorm . val_w. One warp per row.
__global__ void k_lnorm(const float* __restrict__ vw) {
    int lane = threadIdx.x & 31;
    int row = (blockIdx.x * blockDim.x + threadIdx.x) >> 5;
    float z0 = g_x[row * 64 + lane] + g_h[row * 64 + lane];
    float z1 = g_x[row * 64 + 32 + lane] + g_h[row * 64 + 32 + lane];
    float s = z0 + z1;
#pragma unroll
    for (int off = 16; off; off >>= 1) s += __shfl_xor_sync(0xFFFFFFFFu, s, off);
    float mu = s * (1.0f / 64.0f);
    float d0 = z0 - mu, d1 = z1 - mu;
    float v = d0 * d0 + d1 * d1;
#pragma unroll
    for (int off = 16; off; off >>= 1) v += __shfl_xor_sync(0xFFFFFFFFu, v, off);
    float inv = 1.0f / sqrtf(v * (1.0f / 64.0f) + 1e-5f);
    float p = (d0 * inv) * vw[lane] + (d1 * inv) * vw[32 + lane];
#pragma unroll
    for (int off = 16; off; off >>= 1) p += __shfl_xor_sync(0xFFFFFFFFu, p, off);
    if (lane == 0) g_s[row] = p;
}

// out = relu(mean_i(s_i) + val_b). Single block, deterministic tree reduce.
__global__ void k_final(const float* __restrict__ vb, float* __restrict__ out) {
    __shared__ float red[1024];
    int t = threadIdx.x;
    float s = g_s[t] + g_s[t + 1024] + g_s[t + 2048] + g_s[t + 3072];
    red[t] = s;
    __syncthreads();
#pragma unroll
    for (int st = 512; st; st >>= 1) {
        if (t < st) red[t] += red[t + st];
        __syncthreads();
    }
    if (t == 0) {
        float p = red[0] * (1.0f / 4096.0f) + vb[0];
        out[0] = fmaxf(p, 0.f);
    }
}

// ---------------- launch ----------------
extern "C" void kernel_launch(void* const* d_in, const int* in_sizes, int n_in,
                              void* d_out, int out_size) {
    const float* adj    = (const float*)d_in[0];
    const void*  tsp    = d_in[1];
    const float* arr    = (const float*)d_in[2];
    const float* dep    = (const float*)d_in[3];
    const float* hard   = (const float*)d_in[4];
    // d_in[5] = active_agents (all ones, unused by reference math)
    const float* emb_w1 = (const float*)d_in[6];
    const float* emb_b1 = (const float*)d_in[7];
    const float* emb_w2 = (const float*)d_in[8];
    const float* emb_b2 = (const float*)d_in[9];
    const float* gat_w  = (const float*)d_in[10];
    const float* gat_as = (const float*)d_in[11];
    const float* gat_ad = (const float*)d_in[12];
    const float* gat_b  = (const float*)d_in[13];
    const float* val_w  = (const float*)d_in[14];
    const float* val_b  = (const float*)d_in[15];
    float* out = (float*)d_out;

    k_reset<<<16, 256>>>();
    k_build<<<(NAG * NAG / 4) / 256, 256>>>((const float4*)adj);
    k_emb<<<NAG / 16, 256>>>(tsp, arr, dep, hard, emb_w1, emb_b1, emb_w2, emb_b2);

    for (int l = 0; l < 3; l++) {
        k_gemm<<<NAG / 16, 256>>>(gat_w + l * H * H, l == 0 ? 1 : 0);
        k_scores<<<NAG * 32 / 256, 256>>>(gat_as + l * H, gat_ad + l * H);
        k_agg<<<NAG / 8, 256>>>(gat_b + l * H, l < 2 ? 1 : 0);
    }

    k_lnorm<<<NAG * 32 / 256, 256>>>(val_w);
    k_final<<<1, 1024>>>(val_b, out);
}

// round 6
// speedup vs baseline: 1.1510x; 1.1510x over previous
#include <cuda_runtime.h>
#include <cuda_bf16.h>

#define NAG 4096
#define H   64
#define CAP 128   // per-row neighbor capacity (Poisson(32) tail << 128)

// ---------------- device scratch (no allocations allowed) ----------------
__device__ int   g_cnt[NAG];
__device__ int   g_list[NAG * CAP];
__device__ float g_x[NAG * H];     // embedding output (kept for residual)
__device__ float g_h[NAG * H];     // layer io
__device__ float g_hw[NAG * H];    // h @ W
__device__ float g_ssrc[NAG];
__device__ float g_sdst[NAG];
__device__ float g_part[512];      // per-block partials for final reduction
__device__ int   g_ctr;

// ---------------- kernels ----------------

__global__ void k_reset() {
    int i = blockIdx.x * blockDim.x + threadIdx.x;
    if (i < NAG) g_cnt[i] = 0;
    if (i == 0) g_ctr = 0;
}

// mask[i][j] = adj[j][i] != 0 (self-loop handled once in aggregation).
// 32B (2x float4) per thread over the 64MB adjacency, coalesced.
__global__ void k_build(const float4* __restrict__ adj) {
    int t = blockIdx.x * blockDim.x + threadIdx.x;   // 0 .. N*N/8-1
    int j  = t >> 9;            // adjacency row (source node)
    int c0 = (t & 511) << 3;    // column base (destination node)
    float4 v0 = adj[t * 2];
    float4 v1 = adj[t * 2 + 1];
    float vv[8] = {v0.x, v0.y, v0.z, v0.w, v1.x, v1.y, v1.z, v1.w};
#pragma unroll
    for (int q = 0; q < 8; q++) {
        int i = c0 + q;
        if (vv[q] != 0.0f && i != j) {
            int slot = atomicAdd(&g_cnt[i], 1);
            if (slot < CAP) g_list[i * CAP + slot] = j;
        }
    }
}

__device__ __forceinline__ float decode_ts(const void* p) {
    int iv = *(const int*)p;
    if (iv > -1000000 && iv < 1000000) return (float)iv;  // int32 timestep
    return __int_as_float(iv);                            // float32 timestep
}

// x = (feat @ w1 + b1) @ w2 + b2. 32 rows / block, 512 threads, 128 blocks.
__global__ void __launch_bounds__(512) k_emb(
        const void* __restrict__ tsp,
        const float* __restrict__ arr, const float* __restrict__ dep,
        const float* __restrict__ hard,
        const float* __restrict__ w1, const float* __restrict__ b1,
        const float* __restrict__ w2, const float* __restrict__ b2) {
    __shared__ float shW[64 * 64];
    __shared__ float shT[32 * 64];
    int tid = threadIdx.x;
    int r0 = blockIdx.x * 32;
    const float4* W4 = (const float4*)w2;
    ((float4*)shW)[tid] = W4[tid];
    ((float4*)shW)[tid + 512] = W4[tid + 512];
    float ts = decode_ts(tsp);
    int o = tid & 63, rq = tid >> 6;
    int rb = rq * 4;
    float w1a = w1[o], w1b = w1[64 + o], b1v = b1[o];
#pragma unroll
    for (int rr = 0; rr < 4; rr++) {
        int row = r0 + rb + rr;
        float a = arr[row];
        float pg = (ts - a) / (dep[row] - a);
        shT[(rb + rr) * 64 + o] = pg * w1a + hard[row] * w1b + b1v;
    }
    __syncthreads();
    float a0 = 0.f, a1 = 0.f, a2 = 0.f, a3 = 0.f;
#pragma unroll
    for (int k = 0; k < 64; k++) {
        float wv = shW[k * 64 + o];
        a0 += shT[(rb + 0) * 64 + k] * wv;
        a1 += shT[(rb + 1) * 64 + k] * wv;
        a2 += shT[(rb + 2) * 64 + k] * wv;
        a3 += shT[(rb + 3) * 64 + k] * wv;
    }
    float bb = b2[o];
    g_x[(r0 + rb + 0) * 64 + o] = a0 + bb;
    g_x[(r0 + rb + 1) * 64 + o] = a1 + bb;
    g_x[(r0 + rb + 2) * 64 + o] = a2 + bb;
    g_x[(r0 + rb + 3) * 64 + o] = a3 + bb;
}

// hw = in @ W, plus fused attention scores ssrc/sdst. 32 rows/block, 512 thr.
__global__ void __launch_bounds__(512) k_gemm_scores(
        const float* __restrict__ W,
        const float* __restrict__ asrc, const float* __restrict__ adst,
        int in_is_x) {
    __shared__ float shW[64 * 64];
    __shared__ float shIn[32 * 64];
    __shared__ float sred[16][8];
    const float* __restrict__ in = in_is_x ? g_x : g_h;
    int tid = threadIdx.x;
    int r0 = blockIdx.x * 32;
    const float4* W4 = (const float4*)W;
    ((float4*)shW)[tid] = W4[tid];
    ((float4*)shW)[tid + 512] = W4[tid + 512];
    ((float4*)shIn)[tid] = ((const float4*)(in + r0 * 64))[tid];
    __syncthreads();
    int o = tid & 63, rq = tid >> 6;
    int rb = rq * 4;
    float a0 = 0.f, a1 = 0.f, a2 = 0.f, a3 = 0.f;
#pragma unroll
    for (int k = 0; k < 64; k++) {
        float wv = shW[k * 64 + o];
        a0 += shIn[(rb + 0) * 64 + k] * wv;
        a1 += shIn[(rb + 1) * 64 + k] * wv;
        a2 += shIn[(rb + 2) * 64 + k] * wv;
        a3 += shIn[(rb + 3) * 64 + k] * wv;
    }
    g_hw[(r0 + rb + 0) * 64 + o] = a0;
    g_hw[(r0 + rb + 1) * 64 + o] = a1;
    g_hw[(r0 + rb + 2) * 64 + o] = a2;
    g_hw[(r0 + rb + 3) * 64 + o] = a3;
    // fused scores: ssrc[r] = hw[r].asrc, sdst[r] = hw[r].adst
    float vas = asrc[o], vad = adst[o];
    float ps[4] = {a0 * vas, a1 * vas, a2 * vas, a3 * vas};
    float pd[4] = {a0 * vad, a1 * vad, a2 * vad, a3 * vad};
#pragma unroll
    for (int r = 0; r < 4; r++) {
#pragma unroll
        for (int off = 16; off; off >>= 1) {
            ps[r] += __shfl_xor_sync(0xFFFFFFFFu, ps[r], off);
            pd[r] += __shfl_xor_sync(0xFFFFFFFFu, pd[r], off);
        }
    }
    int warp = tid >> 5, lane = tid & 31;
    if (lane == 0) {
#pragma unroll
        for (int r = 0; r < 4; r++) {
            sred[warp][r * 2 + 0] = ps[r];
            sred[warp][r * 2 + 1] = pd[r];
        }
    }
    __syncthreads();
    if (tid < 64) {
        int r = tid >> 1, sc = tid & 1;
        int q = r >> 2, rr = r & 3;
        float v = sred[q * 2][rr * 2 + sc] + sred[q * 2 + 1][rr * 2 + sc];
        if (sc == 0) g_ssrc[r0 + r] = v;
        else         g_sdst[r0 + r] = v;
    }
}

// h[i] = softmax_j(leaky(ssrc[j]+sdst[i])) @ hw + b ; optional relu. Warp/row.
__global__ void __launch_bounds__(256) k_agg(const float* __restrict__ bias,
                                             int dorelu) {
    __shared__ float shw[8][CAP];
    __shared__ int   shj[8][CAP];
    int lane = threadIdx.x & 31;
    int w = threadIdx.x >> 5;
    int row = blockIdx.x * 8 + w;
    int deg = min(g_cnt[row], CAP);
    float sd = g_sdst[row];
    for (int n = lane; n < deg; n += 32) {
        int j = g_list[row * CAP + n];
        float e = g_ssrc[j] + sd;
        e = (e >= 0.f) ? e : 0.2f * e;
        shw[w][n] = e;
        shj[w][n] = j;
    }
    float es = g_ssrc[row] + sd;          // self-loop
    es = (es >= 0.f) ? es : 0.2f * es;
    __syncwarp();
    float m = es;
    for (int n = lane; n < deg; n += 32) m = fmaxf(m, shw[w][n]);
#pragma unroll
    for (int off = 16; off; off >>= 1)
        m = fmaxf(m, __shfl_xor_sync(0xFFFFFFFFu, m, off));
    float part = 0.f;
    for (int n = lane; n < deg; n += 32) {
        float ww = expf(shw[w][n] - m);
        shw[w][n] = ww;
        part += ww;
    }
#pragma unroll
    for (int off = 16; off; off >>= 1)
        part += __shfl_xor_sync(0xFFFFFFFFu, part, off);
    float wself = expf(es - m);
    float denom = part + wself;
    __syncwarp();
    // aggregation: float2 per lane (cols 2*lane, 2*lane+1), 4x unroll,
    // dual accumulators to break the FMA dependency chain.
    const float2* __restrict__ hw2 = (const float2*)g_hw;
    float2 vself = hw2[row * 32 + lane];
    float2 accA = make_float2(wself * vself.x, wself * vself.y);
    float2 accB = make_float2(0.f, 0.f);
    int n = 0;
    for (; n + 4 <= deg; n += 4) {
        float w0 = shw[w][n + 0], w1 = shw[w][n + 1];
        float w2 = shw[w][n + 2], w3 = shw[w][n + 3];
        int j0 = shj[w][n + 0], j1 = shj[w][n + 1];
        int j2 = shj[w][n + 2], j3 = shj[w][n + 3];
        float2 v0 = hw2[j0 * 32 + lane];
        float2 v1 = hw2[j1 * 32 + lane];
        float2 v2 = hw2[j2 * 32 + lane];
        float2 v3 = hw2[j3 * 32 + lane];
        accA.x += w0 * v0.x; accA.y += w0 * v0.y;
        accB.x += w1 * v1.x; accB.y += w1 * v1.y;
        accA.x += w2 * v2.x; accA.y += w2 * v2.y;
        accB.x += w3 * v3.x; accB.y += w3 * v3.y;
    }
    for (; n < deg; n++) {
        float ww = shw[w][n];
        float2 v = hw2[shj[w][n] * 32 + lane];
        accA.x += ww * v.x; accA.y += ww * v.y;
    }
    float inv = 1.f / denom;
    float2 bb = ((const float2*)bias)[lane];
    float o0 = (accA.x + accB.x) * inv + bb.x;
    float o1 = (accA.y + accB.y) * inv + bb.y;
    if (dorelu) { o0 = fmaxf(o0, 0.f); o1 = fmaxf(o1, 0.f); }
    ((float2*)g_h)[row * 32 + lane] = make_float2(o0, o1);
}

// z = x + h ; layernorm(z) ; dot with val_w ; global mean + relu (fused).
// 512 blocks x 8 warps (1 row/warp). Last block does a deterministic
// fixed-order tree reduction over the 512 per-block partials.
__global__ void __launch_bounds__(256) k_lnorm_final(
        const float* __restrict__ vw, const float* __restrict__ vb,
        float* __restrict__ out) {
    __shared__ float warr[8];
    __shared__ float red[256];
    __shared__ int islast;
    int tid = threadIdx.x;
    int lane = tid & 31, w = tid >> 5;
    int row = blockIdx.x * 8 + w;
    float z0 = g_x[row * 64 + lane] + g_h[row * 64 + lane];
    float z1 = g_x[row * 64 + 32 + lane] + g_h[row * 64 + 32 + lane];
    float s = z0 + z1;
#pragma unroll
    for (int off = 16; off; off >>= 1) s += __shfl_xor_sync(0xFFFFFFFFu, s, off);
    float mu = s * (1.0f / 64.0f);
    float d0 = z0 - mu, d1 = z1 - mu;
    float v = d0 * d0 + d1 * d1;
#pragma unroll
    for (int off = 16; off; off >>= 1) v += __shfl_xor_sync(0xFFFFFFFFu, v, off);
    float inv = 1.0f / sqrtf(v * (1.0f / 64.0f) + 1e-5f);
    float p = (d0 * inv) * vw[lane] + (d1 * inv) * vw[32 + lane];
#pragma unroll
    for (int off = 16; off; off >>= 1) p += __shfl_xor_sync(0xFFFFFFFFu, p, off);
    if (lane == 0) warr[w] = p;
    __syncthreads();
    if (tid == 0) {
        float bp = ((warr[0] + warr[1]) + (warr[2] + warr[3]))
                 + ((warr[4] + warr[5]) + (warr[6] + warr[7]));
        g_part[blockIdx.x] = bp;
        __threadfence();
        int t = atomicAdd(&g_ctr, 1);
        islast = (t == (int)gridDim.x - 1);
    }
    __syncthreads();
    if (islast) {
        __threadfence();
        red[tid] = g_part[tid] + g_part[tid + 256];
        __syncthreads();
#pragma unroll
        for (int st = 128; st; st >>= 1) {
            if (tid < st) red[tid] += red[tid + st];
            __syncthreads();
        }
        if (tid == 0) {
            float r = red[0] * (1.0f / 4096.0f) + vb[0];
            out[0] = fmaxf(r, 0.f);
        }
    }
}

// ---------------- launch ----------------
extern "C" void kernel_launch(void* const* d_in, const int* in_sizes, int n_in,
                              void* d_out, int out_size) {
    const float* adj    = (const float*)d_in[0];
    const void*  tsp    = d_in[1];
    const float* arr    = (const float*)d_in[2];
    const float* dep    = (const float*)d_in[3];
    const float* hard   = (const float*)d_in[4];
    // d_in[5] = active_agents (all ones, unused by the reference math)
    const float* emb_w1 = (const float*)d_in[6];
    const float* emb_b1 = (const float*)d_in[7];
    const float* emb_w2 = (const float*)d_in[8];
    const float* emb_b2 = (const float*)d_in[9];
    const float* gat_w  = (const float*)d_in[10];
    const float* gat_as = (const float*)d_in[11];
    const float* gat_ad = (const float*)d_in[12];
    const float* gat_b  = (const float*)d_in[13];
    const float* val_w  = (const float*)d_in[14];
    const float* val_b  = (const float*)d_in[15];
    float* out = (float*)d_out;

    k_reset<<<16, 256>>>();
    k_build<<<(NAG * NAG / 8) / 256, 256>>>((const float4*)adj);
    k_emb<<<NAG / 32, 512>>>(tsp, arr, dep, hard, emb_w1, emb_b1, emb_w2, emb_b2);

    for (int l = 0; l < 3; l++) {
        k_gemm_scores<<<NAG / 32, 512>>>(gat_w + l * H * H, gat_as + l * H,
                                         gat_ad + l * H, l == 0 ? 1 : 0);
        k_agg<<<NAG / 8, 256>>>(gat_b + l * H, l < 2 ? 1 : 0);
    }

    k_lnorm_final<<<NAG / 8, 256>>>(val_w, val_b, out);
}